// round 3
// baseline (speedup 1.0000x reference)
#include <cuda_runtime.h>
#include <cuda_bf16.h>
#include <cuda_fp16.h>
#include <cstdint>

// Problem dims
#define MDIM 8192
#define KDIM 4096
#define NDIM 11008

// Tiling
#define BM 128
#define BN 128
#define BK 64
#define KT (KDIM / BK)        // 64 k-tiles
#define STAGES 3

// Padded smem layout: rows of 64 bf16 padded to 72 (144B) for conflict-free ldmatrix
#define PITCH_B 144
#define TILE_B (128 * PITCH_B)          // 18432 bytes per tile buffer
#define STAGE_B (3 * TILE_B)            // Ahi + Alo + W = 55296
#define SMEM_TOTAL (STAGES * STAGE_B)   // 165888

// ---------------------------------------------------------------------------
// Static scratch (no allocs allowed)
// ---------------------------------------------------------------------------
__device__ __nv_bfloat16 g_Ahi[(size_t)MDIM * KDIM];
__device__ __nv_bfloat16 g_Alo[(size_t)MDIM * KDIM];
__device__ __nv_bfloat16 g_W[(size_t)NDIM * KDIM];

__device__ __forceinline__ uint32_t smem_u32(const void* p) {
    uint32_t a;
    asm("{ .reg .u64 t; cvta.to.shared.u64 t, %1; cvt.u32.u64 %0, t; }" : "=r"(a) : "l"(p));
    return a;
}

__device__ __forceinline__ void cp16(uint32_t s, const void* g) {
    asm volatile("cp.async.cg.shared.global [%0], [%1], 16;" :: "r"(s), "l"(g));
}

__device__ __forceinline__ void ldsm4(uint32_t* r, uint32_t a) {
    asm volatile("ldmatrix.sync.aligned.m8n8.x4.shared.b16 {%0,%1,%2,%3}, [%4];"
                 : "=r"(r[0]), "=r"(r[1]), "=r"(r[2]), "=r"(r[3]) : "r"(a));
}

__device__ __forceinline__ void mma16816(float* d, const uint32_t* a, uint32_t b0, uint32_t b1) {
    asm volatile(
        "mma.sync.aligned.m16n8k16.row.col.f32.bf16.bf16.f32 "
        "{%0,%1,%2,%3}, {%4,%5,%6,%7}, {%8,%9}, {%0,%1,%2,%3};"
        : "+f"(d[0]), "+f"(d[1]), "+f"(d[2]), "+f"(d[3])
        : "r"(a[0]), "r"(a[1]), "r"(a[2]), "r"(a[3]), "r"(b0), "r"(b1));
}

// ---------------------------------------------------------------------------
// Pre-pass converts
// ---------------------------------------------------------------------------
__global__ void __launch_bounds__(256) convert_x_kernel(const float4* __restrict__ x) {
    int i = blockIdx.x * blockDim.x + threadIdx.x;
    if (i >= (MDIM * KDIM / 4)) return;
    float4 v = x[i];
    __nv_bfloat16 h0 = __float2bfloat16_rn(v.x);
    __nv_bfloat16 h1 = __float2bfloat16_rn(v.y);
    __nv_bfloat16 h2 = __float2bfloat16_rn(v.z);
    __nv_bfloat16 h3 = __float2bfloat16_rn(v.w);
    __nv_bfloat16 l0 = __float2bfloat16_rn(v.x - __bfloat162float(h0));
    __nv_bfloat16 l1 = __float2bfloat16_rn(v.y - __bfloat162float(h1));
    __nv_bfloat16 l2 = __float2bfloat16_rn(v.z - __bfloat162float(h2));
    __nv_bfloat16 l3 = __float2bfloat16_rn(v.w - __bfloat162float(h3));
    __nv_bfloat162* hp = reinterpret_cast<__nv_bfloat162*>(g_Ahi);
    __nv_bfloat162* lp = reinterpret_cast<__nv_bfloat162*>(g_Alo);
    __nv_bfloat162 a; a.x = h0; a.y = h1;
    __nv_bfloat162 b; b.x = h2; b.y = h3;
    __nv_bfloat162 c; c.x = l0; c.y = l1;
    __nv_bfloat162 d; d.x = l2; d.y = l3;
    hp[2*i] = a; hp[2*i+1] = b;
    lp[2*i] = c; lp[2*i+1] = d;
}

__global__ void __launch_bounds__(256) convert_w_kernel(const int4* __restrict__ w) {
    int i = blockIdx.x * blockDim.x + threadIdx.x;
    if (i >= (NDIM * KDIM / 4)) return;
    int4 v = w[i];
    __nv_bfloat162 a, b;
    a.x = __float2bfloat16_rn((float)v.x);   // int8 range: exact in bf16
    a.y = __float2bfloat16_rn((float)v.y);
    b.x = __float2bfloat16_rn((float)v.z);
    b.y = __float2bfloat16_rn((float)v.w);
    __nv_bfloat162* wp = reinterpret_cast<__nv_bfloat162*>(g_W);
    wp[2*i] = a; wp[2*i+1] = b;
}

// ---------------------------------------------------------------------------
// Main GEMM: mma.sync bf16 (split hi/lo), cp.async 3-stage pipeline
// 256 threads = 8 warps arranged 4(M) x 2(N); warp tile 32x64
// ---------------------------------------------------------------------------
__global__ void __launch_bounds__(256, 1)
qlinear_gemm(const float* __restrict__ wscale,
             const float* __restrict__ wbias,
             float* __restrict__ out)
{
    extern __shared__ char smem[];
    const uint32_t sb = smem_u32(smem);
    const int tid = threadIdx.x;
    const int wid = tid >> 5;
    const int lane = tid & 31;
    const int m0 = blockIdx.y * BM;
    const int n0 = blockIdx.x * BN;
    const int wm = wid >> 1;   // 0..3
    const int wn = wid & 1;    // 0..1

    const __nv_bfloat16* gAhi = g_Ahi + (size_t)m0 * KDIM;
    const __nv_bfloat16* gAlo = g_Alo + (size_t)m0 * KDIM;
    const __nv_bfloat16* gW   = g_W   + (size_t)n0 * KDIM;

    float acc[2][8][4];
    #pragma unroll
    for (int a = 0; a < 2; a++)
        #pragma unroll
        for (int b = 0; b < 8; b++)
            #pragma unroll
            for (int c = 0; c < 4; c++) acc[a][b][c] = 0.f;

    // per-thread load coords: 1024 16B-chunks per tile, 4 per thread
    const int lrow0 = tid >> 3;       // row advances by 32 per iter
    const int lcol  = tid & 7;        // 16B chunk within 128B row

    auto load_stage = [&](int s, int kt) {
        const uint32_t base = sb + s * STAGE_B;
        const int k0 = kt * BK;
        #pragma unroll
        for (int i = 0; i < 4; i++) {
            const int r = lrow0 + i * 32;
            const uint32_t soff = r * PITCH_B + lcol * 16;
            const size_t goff = (size_t)r * KDIM + k0 + lcol * 8;
            cp16(base + soff,              gAhi + goff);
            cp16(base + TILE_B + soff,     gAlo + goff);
            cp16(base + 2 * TILE_B + soff, gW + goff);
        }
    };

    auto compute_stage = [&](int s) {
        const uint32_t hbase = sb + s * STAGE_B;
        const uint32_t lbase = hbase + TILE_B;
        const uint32_t bbase = hbase + 2 * TILE_B;
        const int lr = lane & 15;
        const int lk = (lane >> 4) * 16;
        #pragma unroll
        for (int ks = 0; ks < 4; ks++) {
            uint32_t ah[2][4], al[2][4], bw[4][4];
            #pragma unroll
            for (int mt = 0; mt < 2; mt++) {
                uint32_t ro = (uint32_t)(wm * 32 + mt * 16 + lr) * PITCH_B + ks * 32 + lk;
                ldsm4(ah[mt], hbase + ro);
                ldsm4(al[mt], lbase + ro);
            }
            #pragma unroll
            for (int nt = 0; nt < 4; nt++) {
                uint32_t ro = (uint32_t)(wn * 64 + nt * 16 + lr) * PITCH_B + ks * 32 + lk;
                ldsm4(bw[nt], bbase + ro);
            }
            #pragma unroll
            for (int mt = 0; mt < 2; mt++) {
                #pragma unroll
                for (int nt = 0; nt < 4; nt++) {
                    mma16816(acc[mt][nt*2+0], ah[mt], bw[nt][0], bw[nt][2]);
                    mma16816(acc[mt][nt*2+0], al[mt], bw[nt][0], bw[nt][2]);
                    mma16816(acc[mt][nt*2+1], ah[mt], bw[nt][1], bw[nt][3]);
                    mma16816(acc[mt][nt*2+1], al[mt], bw[nt][1], bw[nt][3]);
                }
            }
        }
    };

    // Prologue: stages 0,1
    load_stage(0, 0);
    asm volatile("cp.async.commit_group;" ::: "memory");
    load_stage(1, 1);
    asm volatile("cp.async.commit_group;" ::: "memory");

    for (int kt = 0; kt < KT; kt++) {
        asm volatile("cp.async.wait_group 1;" ::: "memory");
        __syncthreads();
        if (kt + 2 < KT) {
            load_stage((kt + 2) % 3, kt + 2);
        }
        asm volatile("cp.async.commit_group;" ::: "memory");
        compute_stage(kt % 3);
    }

    // Epilogue: scale + bias (fp32 inputs), fp32 store
    #pragma unroll
    for (int mt = 0; mt < 2; mt++) {
        const int r0 = m0 + wm * 32 + mt * 16 + (lane >> 2);
        #pragma unroll
        for (int nt = 0; nt < 4; nt++) {
            #pragma unroll
            for (int h = 0; h < 2; h++) {
                const int n = n0 + wn * 64 + nt * 16 + h * 8 + (lane & 3) * 2;
                float2 sf = *reinterpret_cast<const float2*>(wscale + n);
                float2 bf = *reinterpret_cast<const float2*>(wbias + n);
                const float* d = acc[mt][nt*2+h];
                float2 v0, v1;
                v0.x = d[0] * sf.x + bf.x;
                v0.y = d[1] * sf.y + bf.y;
                v1.x = d[2] * sf.x + bf.x;
                v1.y = d[3] * sf.y + bf.y;
                *reinterpret_cast<float2*>(out + (size_t)r0 * NDIM + n) = v0;
                *reinterpret_cast<float2*>(out + (size_t)(r0 + 8) * NDIM + n) = v1;
            }
        }
    }
}

// ---------------------------------------------------------------------------
// Host
// ---------------------------------------------------------------------------
extern "C" void kernel_launch(void* const* d_in, const int* in_sizes, int n_in,
                              void* d_out, int out_size) {
    const float* x  = (const float*)d_in[0];
    const int*   wq = (const int*)d_in[1];
    const float* sc = (const float*)d_in[2];
    const float* bi = (const float*)d_in[3];
    float* out = (float*)d_out;

    convert_x_kernel<<<(MDIM * KDIM / 4 + 255) / 256, 256>>>((const float4*)x);
    convert_w_kernel<<<(NDIM * KDIM / 4 + 255) / 256, 256>>>((const int4*)wq);

    cudaFuncSetAttribute(qlinear_gemm, cudaFuncAttributeMaxDynamicSharedMemorySize, SMEM_TOTAL);
    dim3 grid(NDIM / BN, MDIM / BM);   // (86, 64), n-fastest for W L2 reuse
    qlinear_gemm<<<grid, 256, SMEM_TOTAL>>>(sc, bi, out);
}

// round 4
// speedup vs baseline: 1.8586x; 1.8586x over previous
#include <cuda_runtime.h>
#include <cuda_bf16.h>
#include <cuda_fp16.h>
#include <cstdint>

// Problem dims
#define MDIM 8192
#define KDIM 4096
#define NDIM 11008

// Tiling
#define BM 128
#define BN 128
#define BK 64
#define KT (KDIM / BK)        // 64 k-tiles
#define STAGES 4

// Padded smem layout: rows of 64 fp16 padded to 72 (144B) for conflict-free ldmatrix
#define PITCH_B 144
#define TILE_B (128 * PITCH_B)          // 18432 bytes per tile buffer
#define STAGE_B (2 * TILE_B)            // X + W = 36864
#define SMEM_TOTAL (STAGES * STAGE_B)   // 147456

// ---------------------------------------------------------------------------
// Static scratch (no allocs allowed)
// ---------------------------------------------------------------------------
__device__ __half g_X[(size_t)MDIM * KDIM];
__device__ __half g_W[(size_t)NDIM * KDIM];

__device__ __forceinline__ uint32_t smem_u32(const void* p) {
    uint32_t a;
    asm("{ .reg .u64 t; cvta.to.shared.u64 t, %1; cvt.u32.u64 %0, t; }" : "=r"(a) : "l"(p));
    return a;
}

__device__ __forceinline__ void cp16(uint32_t s, const void* g) {
    asm volatile("cp.async.cg.shared.global [%0], [%1], 16;" :: "r"(s), "l"(g));
}

__device__ __forceinline__ void ldsm4(uint32_t* r, uint32_t a) {
    asm volatile("ldmatrix.sync.aligned.m8n8.x4.shared.b16 {%0,%1,%2,%3}, [%4];"
                 : "=r"(r[0]), "=r"(r[1]), "=r"(r[2]), "=r"(r[3]) : "r"(a));
}

__device__ __forceinline__ void mma16816(float* d, const uint32_t* a, uint32_t b0, uint32_t b1) {
    asm volatile(
        "mma.sync.aligned.m16n8k16.row.col.f32.f16.f16.f32 "
        "{%0,%1,%2,%3}, {%4,%5,%6,%7}, {%8,%9}, {%0,%1,%2,%3};"
        : "+f"(d[0]), "+f"(d[1]), "+f"(d[2]), "+f"(d[3])
        : "r"(a[0]), "r"(a[1]), "r"(a[2]), "r"(a[3]), "r"(b0), "r"(b1));
}

// ---------------------------------------------------------------------------
// Pre-pass converts
// ---------------------------------------------------------------------------
__global__ void __launch_bounds__(256) convert_x_kernel(const float4* __restrict__ x) {
    int i = blockIdx.x * blockDim.x + threadIdx.x;
    if (i >= (MDIM * KDIM / 4)) return;
    float4 v = x[i];
    __half2* xp = reinterpret_cast<__half2*>(g_X);
    __half2 a, b;
    a.x = __float2half_rn(v.x); a.y = __float2half_rn(v.y);
    b.x = __float2half_rn(v.z); b.y = __float2half_rn(v.w);
    xp[2*i] = a; xp[2*i+1] = b;
}

__global__ void __launch_bounds__(256) convert_w_kernel(const int4* __restrict__ w) {
    int i = blockIdx.x * blockDim.x + threadIdx.x;
    if (i >= (NDIM * KDIM / 4)) return;
    int4 v = w[i];
    __half2 a, b;
    a.x = __float2half_rn((float)v.x);   // int8 range: exact in fp16
    a.y = __float2half_rn((float)v.y);
    b.x = __float2half_rn((float)v.z);
    b.y = __float2half_rn((float)v.w);
    __half2* wp = reinterpret_cast<__half2*>(g_W);
    wp[2*i] = a; wp[2*i+1] = b;
}

// ---------------------------------------------------------------------------
// Main GEMM: mma.sync fp16, cp.async 4-stage pipeline
// 256 threads = 8 warps arranged 4(M) x 2(N); warp tile 32x64
// ---------------------------------------------------------------------------
__global__ void __launch_bounds__(256, 1)
qlinear_gemm(const float* __restrict__ wscale,
             const float* __restrict__ wbias,
             float* __restrict__ out)
{
    extern __shared__ char smem[];
    const uint32_t sb = smem_u32(smem);
    const int tid = threadIdx.x;
    const int wid = tid >> 5;
    const int lane = tid & 31;
    const int m0 = blockIdx.y * BM;
    const int n0 = blockIdx.x * BN;
    const int wm = wid >> 1;   // 0..3
    const int wn = wid & 1;    // 0..1

    const __half* gX = g_X + (size_t)m0 * KDIM;
    const __half* gW = g_W + (size_t)n0 * KDIM;

    float acc[2][8][4];
    #pragma unroll
    for (int a = 0; a < 2; a++)
        #pragma unroll
        for (int b = 0; b < 8; b++)
            #pragma unroll
            for (int c = 0; c < 4; c++) acc[a][b][c] = 0.f;

    // per-thread load coords: 1024 16B-chunks per tile, 4 per thread
    const int lrow0 = tid >> 3;       // row advances by 32 per iter
    const int lcol  = tid & 7;        // 16B chunk within 128B row

    auto load_stage = [&](int s, int kt) {
        const uint32_t base = sb + s * STAGE_B;
        const int k0 = kt * BK;
        #pragma unroll
        for (int i = 0; i < 4; i++) {
            const int r = lrow0 + i * 32;
            const uint32_t soff = r * PITCH_B + lcol * 16;
            const size_t goff = (size_t)r * KDIM + k0 + lcol * 8;
            cp16(base + soff,          gX + goff);
            cp16(base + TILE_B + soff, gW + goff);
        }
    };

    auto compute_stage = [&](int s) {
        const uint32_t abase = sb + s * STAGE_B;
        const uint32_t bbase = abase + TILE_B;
        const int lr = lane & 15;
        const int lk = (lane >> 4) * 16;
        #pragma unroll
        for (int ks = 0; ks < 4; ks++) {
            uint32_t ax[2][4], bw[4][4];
            #pragma unroll
            for (int mt = 0; mt < 2; mt++) {
                uint32_t ro = (uint32_t)(wm * 32 + mt * 16 + lr) * PITCH_B + ks * 32 + lk;
                ldsm4(ax[mt], abase + ro);
            }
            #pragma unroll
            for (int nt = 0; nt < 4; nt++) {
                uint32_t ro = (uint32_t)(wn * 64 + nt * 16 + lr) * PITCH_B + ks * 32 + lk;
                ldsm4(bw[nt], bbase + ro);
            }
            #pragma unroll
            for (int mt = 0; mt < 2; mt++) {
                #pragma unroll
                for (int nt = 0; nt < 4; nt++) {
                    mma16816(acc[mt][nt*2+0], ax[mt], bw[nt][0], bw[nt][2]);
                    mma16816(acc[mt][nt*2+1], ax[mt], bw[nt][1], bw[nt][3]);
                }
            }
        }
    };

    // Prologue: stages 0,1,2
    load_stage(0, 0);
    asm volatile("cp.async.commit_group;" ::: "memory");
    load_stage(1, 1);
    asm volatile("cp.async.commit_group;" ::: "memory");
    load_stage(2, 2);
    asm volatile("cp.async.commit_group;" ::: "memory");

    for (int kt = 0; kt < KT; kt++) {
        asm volatile("cp.async.wait_group 2;" ::: "memory");
        __syncthreads();
        if (kt + 3 < KT) {
            load_stage((kt + 3) & 3, kt + 3);
        }
        asm volatile("cp.async.commit_group;" ::: "memory");
        compute_stage(kt & 3);
    }

    // Epilogue: scale + bias (fp32 inputs), fp32 store
    #pragma unroll
    for (int mt = 0; mt < 2; mt++) {
        const int r0 = m0 + wm * 32 + mt * 16 + (lane >> 2);
        #pragma unroll
        for (int nt = 0; nt < 4; nt++) {
            #pragma unroll
            for (int h = 0; h < 2; h++) {
                const int n = n0 + wn * 64 + nt * 16 + h * 8 + (lane & 3) * 2;
                float2 sf = *reinterpret_cast<const float2*>(wscale + n);
                float2 bf = *reinterpret_cast<const float2*>(wbias + n);
                const float* d = acc[mt][nt*2+h];
                float2 v0, v1;
                v0.x = d[0] * sf.x + bf.x;
                v0.y = d[1] * sf.y + bf.y;
                v1.x = d[2] * sf.x + bf.x;
                v1.y = d[3] * sf.y + bf.y;
                *reinterpret_cast<float2*>(out + (size_t)r0 * NDIM + n) = v0;
                *reinterpret_cast<float2*>(out + (size_t)(r0 + 8) * NDIM + n) = v1;
            }
        }
    }
}

// ---------------------------------------------------------------------------
// Host
// ---------------------------------------------------------------------------
extern "C" void kernel_launch(void* const* d_in, const int* in_sizes, int n_in,
                              void* d_out, int out_size) {
    const float* x  = (const float*)d_in[0];
    const int*   wq = (const int*)d_in[1];
    const float* sc = (const float*)d_in[2];
    const float* bi = (const float*)d_in[3];
    float* out = (float*)d_out;

    convert_x_kernel<<<(MDIM * KDIM / 4 + 255) / 256, 256>>>((const float4*)x);
    convert_w_kernel<<<(NDIM * KDIM / 4 + 255) / 256, 256>>>((const int4*)wq);

    cudaFuncSetAttribute(qlinear_gemm, cudaFuncAttributeMaxDynamicSharedMemorySize, SMEM_TOTAL);
    dim3 grid(NDIM / BN, MDIM / BM);   // (86, 64), n-fastest for W L2 reuse
    qlinear_gemm<<<grid, 256, SMEM_TOTAL>>>(sc, bi, out);
}

// round 5
// speedup vs baseline: 1.9784x; 1.0644x over previous
#include <cuda_runtime.h>
#include <cuda_bf16.h>
#include <cuda_fp16.h>
#include <cstdint>

// Problem dims
#define MDIM 8192
#define KDIM 4096
#define NDIM 11008

// Tiling: CTA 256x128x64, 8 warps as 4(M) x 2(N), warp tile 64x64
#define BM 256
#define BN 128
#define BK 64
#define KT (KDIM / BK)        // 64 k-tiles
#define STAGES 4

// Padded smem: rows of 64 fp16 padded to 72 (144B) for conflict-free ldmatrix
#define PITCH_B 144
#define A_TILE_B (BM * PITCH_B)          // 36864
#define W_TILE_B (BN * PITCH_B)          // 18432
#define STAGE_B  (A_TILE_B + W_TILE_B)   // 55296
#define SMEM_TOTAL (STAGES * STAGE_B)    // 221184

// ---------------------------------------------------------------------------
// Static scratch (no allocs allowed)
// ---------------------------------------------------------------------------
__device__ __half g_X[(size_t)MDIM * KDIM];
__device__ __half g_W[(size_t)NDIM * KDIM];

__device__ __forceinline__ uint32_t smem_u32(const void* p) {
    uint32_t a;
    asm("{ .reg .u64 t; cvta.to.shared.u64 t, %1; cvt.u32.u64 %0, t; }" : "=r"(a) : "l"(p));
    return a;
}

__device__ __forceinline__ void cp16(uint32_t s, const void* g) {
    asm volatile("cp.async.cg.shared.global [%0], [%1], 16;" :: "r"(s), "l"(g));
}

__device__ __forceinline__ void ldsm4(uint32_t* r, uint32_t a) {
    asm volatile("ldmatrix.sync.aligned.m8n8.x4.shared.b16 {%0,%1,%2,%3}, [%4];"
                 : "=r"(r[0]), "=r"(r[1]), "=r"(r[2]), "=r"(r[3]) : "r"(a));
}

__device__ __forceinline__ void mma16816(float* d, const uint32_t* a, uint32_t b0, uint32_t b1) {
    asm volatile(
        "mma.sync.aligned.m16n8k16.row.col.f32.f16.f16.f32 "
        "{%0,%1,%2,%3}, {%4,%5,%6,%7}, {%8,%9}, {%0,%1,%2,%3};"
        : "+f"(d[0]), "+f"(d[1]), "+f"(d[2]), "+f"(d[3])
        : "r"(a[0]), "r"(a[1]), "r"(a[2]), "r"(a[3]), "r"(b0), "r"(b1));
}

// ---------------------------------------------------------------------------
// Pre-pass converts
// ---------------------------------------------------------------------------
__global__ void __launch_bounds__(256) convert_x_kernel(const float4* __restrict__ x) {
    int i = blockIdx.x * blockDim.x + threadIdx.x;
    if (i >= (MDIM * KDIM / 4)) return;
    float4 v = x[i];
    __half2* xp = reinterpret_cast<__half2*>(g_X);
    __half2 a, b;
    a.x = __float2half_rn(v.x); a.y = __float2half_rn(v.y);
    b.x = __float2half_rn(v.z); b.y = __float2half_rn(v.w);
    xp[2*i] = a; xp[2*i+1] = b;
}

__global__ void __launch_bounds__(256) convert_w_kernel(const int4* __restrict__ w) {
    int i = blockIdx.x * blockDim.x + threadIdx.x;
    if (i >= (NDIM * KDIM / 4)) return;
    int4 v = w[i];
    __half2 a, b;
    a.x = __float2half_rn((float)v.x);   // int8 range: exact in fp16
    a.y = __float2half_rn((float)v.y);
    b.x = __float2half_rn((float)v.z);
    b.y = __float2half_rn((float)v.w);
    __half2* wp = reinterpret_cast<__half2*>(g_W);
    wp[2*i] = a; wp[2*i+1] = b;
}

// ---------------------------------------------------------------------------
// Main GEMM: mma.sync fp16, cp.async 4-stage pipeline, warp tile 64x64
// ---------------------------------------------------------------------------
__global__ void __launch_bounds__(256, 1)
qlinear_gemm(const float* __restrict__ wscale,
             const float* __restrict__ wbias,
             float* __restrict__ out)
{
    extern __shared__ char smem[];
    const uint32_t sb = smem_u32(smem);
    const int tid = threadIdx.x;
    const int wid = tid >> 5;
    const int lane = tid & 31;
    const int m0 = blockIdx.y * BM;
    const int n0 = blockIdx.x * BN;
    const int wm = wid >> 1;   // 0..3 -> 64 rows each
    const int wn = wid & 1;    // 0..1 -> 64 cols each

    const __half* gX = g_X + (size_t)m0 * KDIM;
    const __half* gW = g_W + (size_t)n0 * KDIM;

    float acc[4][8][4];
    #pragma unroll
    for (int a = 0; a < 4; a++)
        #pragma unroll
        for (int b = 0; b < 8; b++)
            #pragma unroll
            for (int c = 0; c < 4; c++) acc[a][b][c] = 0.f;

    // per-thread load coords: 16B chunks; A: 2048 chunks, W: 1024 chunks
    const int lrow0 = tid >> 3;       // 0..31
    const int lcol  = tid & 7;        // 16B chunk within 128B row

    auto load_stage = [&](int s, int kt) {
        const uint32_t base = sb + s * STAGE_B;
        const int k0 = kt * BK;
        #pragma unroll
        for (int i = 0; i < 8; i++) {
            const int r = lrow0 + i * 32;
            cp16(base + r * PITCH_B + lcol * 16, gX + (size_t)r * KDIM + k0 + lcol * 8);
        }
        #pragma unroll
        for (int i = 0; i < 4; i++) {
            const int r = lrow0 + i * 32;
            cp16(base + A_TILE_B + r * PITCH_B + lcol * 16, gW + (size_t)r * KDIM + k0 + lcol * 8);
        }
    };

    auto compute_stage = [&](int s) {
        const uint32_t abase = sb + s * STAGE_B;
        const uint32_t bbase = abase + A_TILE_B;
        const int lr = lane & 15;
        const int lk = (lane >> 4) * 16;
        #pragma unroll
        for (int ks = 0; ks < 4; ks++) {
            uint32_t af[4][4], bf[4][4];
            #pragma unroll
            for (int mt = 0; mt < 4; mt++) {
                uint32_t ro = (uint32_t)(wm * 64 + mt * 16 + lr) * PITCH_B + ks * 32 + lk;
                ldsm4(af[mt], abase + ro);
            }
            #pragma unroll
            for (int nt = 0; nt < 4; nt++) {
                uint32_t ro = (uint32_t)(wn * 64 + nt * 16 + lr) * PITCH_B + ks * 32 + lk;
                ldsm4(bf[nt], bbase + ro);
            }
            #pragma unroll
            for (int mt = 0; mt < 4; mt++) {
                #pragma unroll
                for (int nt = 0; nt < 4; nt++) {
                    mma16816(acc[mt][nt*2+0], af[mt], bf[nt][0], bf[nt][2]);
                    mma16816(acc[mt][nt*2+1], af[mt], bf[nt][1], bf[nt][3]);
                }
            }
        }
    };

    // Prologue: stages 0,1,2
    load_stage(0, 0);
    asm volatile("cp.async.commit_group;" ::: "memory");
    load_stage(1, 1);
    asm volatile("cp.async.commit_group;" ::: "memory");
    load_stage(2, 2);
    asm volatile("cp.async.commit_group;" ::: "memory");

    for (int kt = 0; kt < KT; kt++) {
        asm volatile("cp.async.wait_group 2;" ::: "memory");
        __syncthreads();
        if (kt + 3 < KT) {
            load_stage((kt + 3) & 3, kt + 3);
        }
        asm volatile("cp.async.commit_group;" ::: "memory");
        compute_stage(kt & 3);
    }

    // Epilogue: scale + bias (fp32 inputs), fp32 store
    #pragma unroll
    for (int mt = 0; mt < 4; mt++) {
        const int r0 = m0 + wm * 64 + mt * 16 + (lane >> 2);
        #pragma unroll
        for (int nt = 0; nt < 4; nt++) {
            #pragma unroll
            for (int h = 0; h < 2; h++) {
                const int n = n0 + wn * 64 + nt * 16 + h * 8 + (lane & 3) * 2;
                float2 sf = *reinterpret_cast<const float2*>(wscale + n);
                float2 bf = *reinterpret_cast<const float2*>(wbias + n);
                const float* d = acc[mt][nt*2+h];
                float2 v0, v1;
                v0.x = d[0] * sf.x + bf.x;
                v0.y = d[1] * sf.y + bf.y;
                v1.x = d[2] * sf.x + bf.x;
                v1.y = d[3] * sf.y + bf.y;
                *reinterpret_cast<float2*>(out + (size_t)r0 * NDIM + n) = v0;
                *reinterpret_cast<float2*>(out + (size_t)(r0 + 8) * NDIM + n) = v1;
            }
        }
    }
}

// ---------------------------------------------------------------------------
// Host
// ---------------------------------------------------------------------------
extern "C" void kernel_launch(void* const* d_in, const int* in_sizes, int n_in,
                              void* d_out, int out_size) {
    const float* x  = (const float*)d_in[0];
    const int*   wq = (const int*)d_in[1];
    const float* sc = (const float*)d_in[2];
    const float* bi = (const float*)d_in[3];
    float* out = (float*)d_out;

    convert_x_kernel<<<(MDIM * KDIM / 4 + 255) / 256, 256>>>((const float4*)x);
    convert_w_kernel<<<(NDIM * KDIM / 4 + 255) / 256, 256>>>((const int4*)wq);

    cudaFuncSetAttribute(qlinear_gemm, cudaFuncAttributeMaxDynamicSharedMemorySize, SMEM_TOTAL);
    dim3 grid(NDIM / BN, MDIM / BM);   // (86, 32), n-fastest for W L2 reuse
    qlinear_gemm<<<grid, 256, SMEM_TOTAL>>>(sc, bi, out);
}